// round 6
// baseline (speedup 1.0000x reference)
#include <cuda_runtime.h>
#include <cuda_bf16.h>

// Problem constants (fixed by the dataset instance)
#define S_  6        // cameras
#define N_  16384    // queries
#define C_  128      // channels
#define H_  4        // heads
#define CH  32       // channels per head
#define P_  8        // sampling points
#define Z_  8        // z-anchors (P//Z == 1, point p uses anchor p)
#define HF  28
#define WF  50
#define M_  (HF*WF)  // 1400 value tokens

// Projected value cache: [s][h][m][ch], bf16 so each (s,h,m) row is a 64B line.
__device__ __nv_bfloat16 g_vproj[S_ * H_ * M_ * CH];

// ---------------------------------------------------------------------------
// Kernel 1: value projection  v[s,m,:] = value[s,m,0,:] @ Wv + bv  (-> bf16)
// One block per (s,m); thread t = output channel.
// ---------------------------------------------------------------------------
__global__ __launch_bounds__(128) void vproj_kernel(
    const float* __restrict__ value,   // (S, M, 1, C)
    const float* __restrict__ Wv,      // (C, C)
    const float* __restrict__ bv)      // (C,)
{
    const int sm = blockIdx.x;         // s*M + m
    const int t  = threadIdx.x;
    __shared__ float vs[C_];
    vs[t] = value[sm * C_ + t];
    __syncthreads();

    float acc = bv[t];
#pragma unroll 8
    for (int k = 0; k < C_; k++)
        acc = fmaf(vs[k], Wv[k * C_ + t], acc);

    const int s = sm / M_;
    const int m = sm - s * M_;
    const int h = t >> 5, ch = t & 31;
    g_vproj[((s * H_ + h) * M_ + m) * CH + ch] = __float2bfloat16(acc);
}

// ---------------------------------------------------------------------------
// Kernel 2: fused deformable attention + output projection.
// One 128-thread block per query n. Warp w handles head w (lane = channel).
// ---------------------------------------------------------------------------
__global__ __launch_bounds__(128) void bevformer_main_kernel(
    const float* __restrict__ query,     // (1, N, C)
    const float* __restrict__ query_pos, // (1, N, C)
    const float* __restrict__ ref,       // (S, 1, N, Z, 2)
    const int*   __restrict__ mask,      // (S, 1, N, Z) as 4-byte words (int32 or f32 1.0)
    const float* __restrict__ Wo,        // (C, 64)
    const float* __restrict__ bo,        // (64,)
    const float* __restrict__ Wa,        // (C, 32)
    const float* __restrict__ ba,        // (32,)
    const float* __restrict__ Wout,      // (C, C)
    const float* __restrict__ bout,      // (C,)
    float*       __restrict__ out)       // (1, N, C)
{
    const int n = blockIdx.x;
    const int t = threadIdx.x;

    __shared__ float qs[C_];           // q + query_pos
    __shared__ float off_sh[H_ * P_ * 2];
    __shared__ float attn_sh[H_ * P_]; // logits then softmax probs
    __shared__ int   sidx[H_ * P_][4];
    __shared__ float sw  [H_ * P_][4];
    __shared__ int   smask;
    __shared__ float ssl[C_];          // normalized slots

    const float q0 = query[n * C_ + t];     // keep for residual
    qs[t] = q0 + query_pos[n * C_ + t];
    __syncthreads();

    // --- sampling offsets (64 outs, warps 0-1) and attn logits (32, warp 2) ---
    if (t < 64) {
        float a = bo[t];
#pragma unroll 8
        for (int k = 0; k < C_; k++) a = fmaf(qs[k], Wo[k * 64 + t], a);
        off_sh[t] = a;
    } else if (t < 96) {
        const int j = t - 64;
        float a = ba[j];
#pragma unroll 8
        for (int k = 0; k < C_; k++) a = fmaf(qs[k], Wa[k * 32 + j], a);
        attn_sh[j] = a;
    }
    __syncthreads();

    // --- softmax over P within each head (lanes 0-31, groups of 8 lanes) ---
    if (t < 32) {
        float l  = attn_sh[t];
        float mx = l;
        mx = fmaxf(mx, __shfl_xor_sync(0xffffffffu, mx, 1));
        mx = fmaxf(mx, __shfl_xor_sync(0xffffffffu, mx, 2));
        mx = fmaxf(mx, __shfl_xor_sync(0xffffffffu, mx, 4));
        float e = expf(l - mx);
        float sm = e;
        sm += __shfl_xor_sync(0xffffffffu, sm, 1);
        sm += __shfl_xor_sync(0xffffffffu, sm, 2);
        sm += __shfl_xor_sync(0xffffffffu, sm, 4);
        attn_sh[t] = e / sm;
    }

    float slots = 0.0f;
    int   cnt   = 0;
    const int h = t >> 5, ch = t & 31;

    for (int s = 0; s < S_; s++) {
        __syncthreads();  // retire previous-iter readers of sidx/sw (also covers softmax)
        if (t < 32) {
            // one (head, point) per lane: bilinear params, attn & validity folded in
            const int hh = t >> 3, p = t & 7;
            const float rx = ref[((s * N_ + n) * Z_ + p) * 2 + 0];
            const float ry = ref[((s * N_ + n) * Z_ + p) * 2 + 1];
            const float x = (rx + off_sh[(hh * P_ + p) * 2 + 0] * (1.0f / WF)) * WF - 0.5f;
            const float y = (ry + off_sh[(hh * P_ + p) * 2 + 1] * (1.0f / HF)) * HF - 0.5f;
            const float xf = floorf(x), yf = floorf(y);
            const float fx = x - xf,    fy = y - yf;
            const int   x0 = (int)xf,   y0 = (int)yf;
            const float a  = attn_sh[t];
#pragma unroll
            for (int cy = 0; cy < 2; cy++) {
#pragma unroll
                for (int cx = 0; cx < 2; cx++) {
                    const int xx = x0 + cx, yy = y0 + cy;
                    const bool valid = (xx >= 0) & (xx < WF) & (yy >= 0) & (yy < HF);
                    const float w = (cx ? fx : 1.0f - fx) * (cy ? fy : 1.0f - fy);
                    const int xc = min(max(xx, 0), WF - 1);
                    const int yc = min(max(yy, 0), HF - 1);
                    sidx[t][cy * 2 + cx] = yc * WF + xc;
                    sw  [t][cy * 2 + cx] = valid ? a * w : 0.0f;
                }
            }
        } else if (t == 32) {
            int mq = 0;
            const int* mp = mask + (s * N_ + n) * Z_;
#pragma unroll
            for (int z = 0; z < Z_; z++) mq |= mp[z];
            smask = (mq != 0);
        }
        __syncthreads();

        if (smask) {
            const __nv_bfloat16* vp = g_vproj + (size_t)((s * H_ + h) * M_) * CH + ch;
            float acc = 0.0f;
#pragma unroll
            for (int p = 0; p < P_; p++) {
                const int j = h * P_ + p;
#pragma unroll
                for (int c4 = 0; c4 < 4; c4++) {
                    const float w  = sw[j][c4];          // broadcast within warp
                    const int   ix = sidx[j][c4];
                    acc = fmaf(w, __bfloat162float(vp[ix * CH]), acc);
                }
            }
            slots += acc;
            cnt   += 1;
        }
    }

    // normalize by hit count (clamp >= 1), then output projection + residual
    ssl[t] = slots / fmaxf((float)cnt, 1.0f);
    __syncthreads();

    float o = bout[t] + q0;
#pragma unroll 8
    for (int k = 0; k < C_; k++)
        o = fmaf(ssl[k], Wout[k * C_ + t], o);
    out[n * C_ + t] = o;
}

// ---------------------------------------------------------------------------
// Launch. Input order (metadata): query, query_pos, value, reference_points_cam,
// bev_mask, Wv, bv, Wo, bo, Wa, ba, Wout, bout, Hf, Wf
// ---------------------------------------------------------------------------
extern "C" void kernel_launch(void* const* d_in, const int* in_sizes, int n_in,
                              void* d_out, int out_size)
{
    const float* query     = (const float*)d_in[0];
    const float* query_pos = (const float*)d_in[1];
    const float* value     = (const float*)d_in[2];
    const float* refpts    = (const float*)d_in[3];
    const int*   bev_mask  = (const int*)  d_in[4];   // bool normalized to 4-byte; !=0 test
    const float* Wv        = (const float*)d_in[5];
    const float* bv        = (const float*)d_in[6];
    const float* Wo        = (const float*)d_in[7];
    const float* bo        = (const float*)d_in[8];
    const float* Wa        = (const float*)d_in[9];
    const float* ba        = (const float*)d_in[10];
    const float* Wout      = (const float*)d_in[11];
    const float* bout      = (const float*)d_in[12];
    float* out = (float*)d_out;

    vproj_kernel<<<S_ * M_, 128>>>(value, Wv, bv);
    bevformer_main_kernel<<<N_, 128>>>(query, query_pos, refpts, bev_mask,
                                       Wo, bo, Wa, ba, Wout, bout, out);
}

// round 7
// speedup vs baseline: 1.3803x; 1.3803x over previous
#include <cuda_runtime.h>
#include <cuda_bf16.h>

// Problem constants (fixed by the dataset instance)
#define S_  6        // cameras
#define N_  16384    // queries
#define C_  128      // channels
#define H_  4        // heads
#define CH  32       // channels per head
#define P_  8        // sampling points
#define Z_  8        // z-anchors (P//Z == 1, point p uses anchor p)
#define HF  28
#define WF  50
#define M_  (HF*WF)  // 1400 value tokens
#define QPB 4        // queries per block

// Projected value cache: [s][h][m][ch], bf16 so each (s,h,m) row is a 64B line.
__device__ __nv_bfloat16 g_vproj[S_ * H_ * M_ * CH];

// ---------------------------------------------------------------------------
// Kernel 1: value projection  v[s,m,:] = value[s,m,0,:] @ Wv + bv  (-> bf16)
// 4 tokens per block to amortize Wv loads; thread t = output channel.
// ---------------------------------------------------------------------------
__global__ __launch_bounds__(128) void vproj_kernel(
    const float* __restrict__ value,   // (S, M, 1, C)
    const float* __restrict__ Wv,      // (C, C)
    const float* __restrict__ bv)      // (C,)
{
    const int sm0 = blockIdx.x * QPB;
    const int t   = threadIdx.x;
    __shared__ float vs[QPB][C_];
#pragma unroll
    for (int qi = 0; qi < QPB; qi++)
        vs[qi][t] = value[(sm0 + qi) * C_ + t];
    __syncthreads();

    float acc[QPB];
    const float b = bv[t];
#pragma unroll
    for (int qi = 0; qi < QPB; qi++) acc[qi] = b;
#pragma unroll 4
    for (int k = 0; k < C_; k++) {
        const float w = Wv[k * C_ + t];
#pragma unroll
        for (int qi = 0; qi < QPB; qi++)
            acc[qi] = fmaf(vs[qi][k], w, acc[qi]);
    }

    const int h = t >> 5, ch = t & 31;
#pragma unroll
    for (int qi = 0; qi < QPB; qi++) {
        const int sm = sm0 + qi;
        const int s = sm / M_;
        const int m = sm - s * M_;
        g_vproj[((s * H_ + h) * M_ + m) * CH + ch] = __float2bfloat16(acc[qi]);
    }
}

// ---------------------------------------------------------------------------
// Kernel 2: fused deformable attention + output projection.
// 128 threads, QPB=4 queries per block.
//  Phase A: load q+pos for 4 queries.
//  Phase B: Wo/Wa matvecs with 4 accumulators (amortized weight loads).
//  Phase C: warp qi = query qi: softmax (registers) + all-cam bilinear params
//           packed as float4/int4 into SMEM.
//  Phase D: warp h = head h: gather-accumulate for all 4 queries, 6 cams.
//  Phase E: Wout matvec with 4 accumulators + residual.
// ---------------------------------------------------------------------------
__global__ __launch_bounds__(128) void bevformer_main_kernel(
    const float* __restrict__ query,     // (1, N, C)
    const float* __restrict__ query_pos, // (1, N, C)
    const float* __restrict__ ref,       // (S, 1, N, Z, 2)
    const int*   __restrict__ mask,      // (S, 1, N, Z) as 4-byte words
    const float* __restrict__ Wo,        // (C, 64)
    const float* __restrict__ bo,        // (64,)
    const float* __restrict__ Wa,        // (C, 32)
    const float* __restrict__ ba,        // (32,)
    const float* __restrict__ Wout,      // (C, C)
    const float* __restrict__ bout,      // (C,)
    float*       __restrict__ out)       // (1, N, C)
{
    const int nb   = blockIdx.x * QPB;
    const int t    = threadIdx.x;
    const int warp = t >> 5, lane = t & 31;

    __shared__ float  qs[QPB][C_];            // q + query_pos
    __shared__ float  off_sh[QPB][64];
    __shared__ float  attn_sh[QPB][32];       // logits (softmax stays in regs)
    __shared__ float4 sw4 [QPB][S_][32];      // corner weights (attn*bilin*valid)
    __shared__ int4   six4[QPB][S_][32];      // corner indices (clamped)
    __shared__ int    smaskA[QPB][S_];        // query hits cam s?
    __shared__ float  ssl[QPB][C_];           // normalized slots

    // ---- Phase A ----
#pragma unroll
    for (int qi = 0; qi < QPB; qi++)
        qs[qi][t] = query[(nb + qi) * C_ + t] + query_pos[(nb + qi) * C_ + t];
    __syncthreads();

    // ---- Phase B: offsets (64 outs) + attn logits (32 outs), x4 queries ----
    if (t < 64) {
        float acc[QPB];
        const float b = bo[t];
#pragma unroll
        for (int qi = 0; qi < QPB; qi++) acc[qi] = b;
#pragma unroll 4
        for (int k = 0; k < C_; k++) {
            const float w = Wo[k * 64 + t];
#pragma unroll
            for (int qi = 0; qi < QPB; qi++)
                acc[qi] = fmaf(qs[qi][k], w, acc[qi]);
        }
#pragma unroll
        for (int qi = 0; qi < QPB; qi++) off_sh[qi][t] = acc[qi];
    } else if (t < 96) {
        const int j = t - 64;
        float acc[QPB];
        const float b = ba[j];
#pragma unroll
        for (int qi = 0; qi < QPB; qi++) acc[qi] = b;
#pragma unroll 4
        for (int k = 0; k < C_; k++) {
            const float w = Wa[k * 32 + j];
#pragma unroll
            for (int qi = 0; qi < QPB; qi++)
                acc[qi] = fmaf(qs[qi][k], w, acc[qi]);
        }
#pragma unroll
        for (int qi = 0; qi < QPB; qi++) attn_sh[qi][j] = acc[qi];
    }
    __syncthreads();

    // ---- Phase C: warp qi handles query qi ----
    {
        const int qi = warp;              // QPB == 4 == num warps
        const int n  = nb + qi;
        const int p  = lane & 7;          // lane = hh*8 + p

        // softmax over the 8 points of this head (groups of 8 lanes)
        float l  = attn_sh[qi][lane];
        float mx = l;
        mx = fmaxf(mx, __shfl_xor_sync(0xffffffffu, mx, 1));
        mx = fmaxf(mx, __shfl_xor_sync(0xffffffffu, mx, 2));
        mx = fmaxf(mx, __shfl_xor_sync(0xffffffffu, mx, 4));
        float e  = expf(l - mx);
        float sm = e;
        sm += __shfl_xor_sync(0xffffffffu, sm, 1);
        sm += __shfl_xor_sync(0xffffffffu, sm, 2);
        sm += __shfl_xor_sync(0xffffffffu, sm, 4);
        const float aprob = e / sm;

        const float ox = off_sh[qi][lane * 2 + 0] * (1.0f / WF);
        const float oy = off_sh[qi][lane * 2 + 1] * (1.0f / HF);

#pragma unroll
        for (int s = 0; s < S_; s++) {
            const float rx = ref[((s * N_ + n) * Z_ + p) * 2 + 0];
            const float ry = ref[((s * N_ + n) * Z_ + p) * 2 + 1];
            const float x = (rx + ox) * WF - 0.5f;
            const float y = (ry + oy) * HF - 0.5f;
            const float xf = floorf(x), yf = floorf(y);
            const float fx = x - xf,    fy = y - yf;
            const int   x0 = (int)xf,   y0 = (int)yf;

            float wv[4]; int iv[4];
#pragma unroll
            for (int cy = 0; cy < 2; cy++) {
#pragma unroll
                for (int cx = 0; cx < 2; cx++) {
                    const int xx = x0 + cx, yy = y0 + cy;
                    const bool valid = (xx >= 0) & (xx < WF) & (yy >= 0) & (yy < HF);
                    const float w = (cx ? fx : 1.0f - fx) * (cy ? fy : 1.0f - fy);
                    const int xc = min(max(xx, 0), WF - 1);
                    const int yc = min(max(yy, 0), HF - 1);
                    iv[cy * 2 + cx] = yc * WF + xc;
                    wv[cy * 2 + cx] = valid ? aprob * w : 0.0f;
                }
            }
            sw4 [qi][s][lane] = make_float4(wv[0], wv[1], wv[2], wv[3]);
            six4[qi][s][lane] = make_int4  (iv[0], iv[1], iv[2], iv[3]);

            // mask: any of the Z=8 words nonzero?
            int word = 0;
            if (lane < Z_) word = mask[(s * N_ + n) * Z_ + lane];
            const int any = __any_sync(0xffffffffu, word != 0);
            if (lane == 0) smaskA[qi][s] = any;
        }
    }
    __syncthreads();

    // ---- Phase D: warp h = head h; gather all queries, all cams ----
    {
        const int h = warp, ch = lane;
        float slots[QPB] = {0.f, 0.f, 0.f, 0.f};
#pragma unroll
        for (int s = 0; s < S_; s++) {
            const __nv_bfloat16* __restrict__ vp =
                g_vproj + (size_t)((s * H_ + h) * M_) * CH + ch;
#pragma unroll
            for (int qi = 0; qi < QPB; qi++) {
                if (!smaskA[qi][s]) continue;
                float acc = 0.0f;
#pragma unroll
                for (int p = 0; p < P_; p++) {
                    const float4 w4 = sw4 [qi][s][h * 8 + p];
                    const int4   i4 = six4[qi][s][h * 8 + p];
                    acc = fmaf(w4.x, __bfloat162float(vp[i4.x * CH]), acc);
                    acc = fmaf(w4.y, __bfloat162float(vp[i4.y * CH]), acc);
                    acc = fmaf(w4.z, __bfloat162float(vp[i4.z * CH]), acc);
                    acc = fmaf(w4.w, __bfloat162float(vp[i4.w * CH]), acc);
                }
                slots[qi] += acc;
            }
        }
#pragma unroll
        for (int qi = 0; qi < QPB; qi++) {
            int cnt = 0;
#pragma unroll
            for (int s = 0; s < S_; s++) cnt += smaskA[qi][s];
            ssl[qi][h * 32 + ch] = slots[qi] / fmaxf((float)cnt, 1.0f);
        }
    }
    __syncthreads();

    // ---- Phase E: output projection + residual, x4 queries ----
    {
        float o[QPB];
        const float b = bout[t];
#pragma unroll
        for (int qi = 0; qi < QPB; qi++)
            o[qi] = b + query[(nb + qi) * C_ + t];
#pragma unroll 4
        for (int k = 0; k < C_; k++) {
            const float w = Wout[k * C_ + t];
#pragma unroll
            for (int qi = 0; qi < QPB; qi++)
                o[qi] = fmaf(ssl[qi][k], w, o[qi]);
        }
#pragma unroll
        for (int qi = 0; qi < QPB; qi++)
            out[(nb + qi) * C_ + t] = o[qi];
    }
}

// ---------------------------------------------------------------------------
// Launch. Input order (metadata): query, query_pos, value, reference_points_cam,
// bev_mask, Wv, bv, Wo, bo, Wa, ba, Wout, bout, Hf, Wf
// ---------------------------------------------------------------------------
extern "C" void kernel_launch(void* const* d_in, const int* in_sizes, int n_in,
                              void* d_out, int out_size)
{
    const float* query     = (const float*)d_in[0];
    const float* query_pos = (const float*)d_in[1];
    const float* value     = (const float*)d_in[2];
    const float* refpts    = (const float*)d_in[3];
    const int*   bev_mask  = (const int*)  d_in[4];
    const float* Wv        = (const float*)d_in[5];
    const float* bv        = (const float*)d_in[6];
    const float* Wo        = (const float*)d_in[7];
    const float* bo        = (const float*)d_in[8];
    const float* Wa        = (const float*)d_in[9];
    const float* ba        = (const float*)d_in[10];
    const float* Wout      = (const float*)d_in[11];
    const float* bout      = (const float*)d_in[12];
    float* out = (float*)d_out;

    vproj_kernel<<<(S_ * M_) / QPB, 128>>>(value, Wv, bv);
    bevformer_main_kernel<<<N_ / QPB, 128>>>(query, query_pos, refpts, bev_mask,
                                             Wo, bo, Wa, ba, Wout, bout, out);
}